// round 10
// baseline (speedup 1.0000x reference)
#include <cuda_runtime.h>
#include <cstdint>

#define BB 64
#define SS 512
#define HH 1024
#define LL 9
#define NC 16
#define CHUNK 32

#define RPB 32          // rows per block in k_logits
#define KT4 32          // float4 columns per K stage (128 floats)
#define NSTAGE 8        // 1024 / 128

// scratch (static __device__ — no allocations)
__device__ float g_logits[BB*SS*LL];     // [B,S,L] fc outputs
__device__ float g_chunks[BB*NC*81];     // per-(batch,chunk) 9x9 log-semiring transfer matrices
__device__ float g_pb[BB];               // per-batch (norm - score)
__device__ int   g_ticket;               // last-block ticket for fused mean

__device__ __forceinline__ void cp_async16(void* smem_dst, const void* gmem_src) {
    unsigned int d = (unsigned int)__cvta_generic_to_shared(smem_dst);
    asm volatile("cp.async.cg.shared.global [%0], [%1], 16;\n"
                 :: "r"(d), "l"(gmem_src) : "memory");
}
__device__ __forceinline__ void cp_commit() {
    asm volatile("cp.async.commit_group;\n" ::: "memory");
}
__device__ __forceinline__ void cp_wait1() {
    asm volatile("cp.async.wait_group 1;\n" ::: "memory");
}
__device__ __forceinline__ void cp_wait0() {
    asm volatile("cp.async.wait_group 0;\n" ::: "memory");
}

// ---------------------------------------------------------------------------
// Kernel 1: logits[b,s,j] = dot(inputs[b,s,:], W[j,:]) + bias[j]
// cp.async double-buffered pipeline: X tiles (32 rows x 128 floats = 16 KB)
// stream into SMEM while FFMA consumes the previous stage. W (36 KB) in SMEM.
// 8 warps x 4 rows. Dynamic smem = 36 + 2*16 = 68 KB, 3 CTAs/SM.
// Column order per lane identical to the non-pipelined version (bit-exact).
// ---------------------------------------------------------------------------
__global__ __launch_bounds__(256, 3) void k_logits(const float* __restrict__ X,
                                                   const float* __restrict__ W,
                                                   const float* __restrict__ bias) {
    extern __shared__ float4 sh[];
    float4* Wsh = sh;                       // LL*(HH/4) = 2304 float4 (36 KB)
    float4* Xsh = sh + LL*(HH/4);           // 2 stages * RPB*KT4 = 2048 float4 (32 KB)

    const int tid  = threadIdx.x;
    const int warp = tid >> 5;
    const int lane = tid & 31;
    const int row0 = blockIdx.x * RPB;
    const float4* X4 = reinterpret_cast<const float4*>(X);
    const float4* W4 = reinterpret_cast<const float4*>(W);

    // prologue: kick off stage 0 X copy before anything else
    {
        #pragma unroll
        for (int i = 0; i < 4; i++) {
            const int c   = tid + 256*i;        // 0..1023 chunk id
            const int r   = c >> 5;             // row within tile
            const int col = c & 31;             // float4 col within stage
            cp_async16(&Xsh[c], &X4[(size_t)(row0 + r)*(HH/4) + col]);
        }
        cp_commit();
    }

    // stage W into smem (L2-resident after first wave)
    for (int idx = tid; idx < LL*(HH/4); idx += 256) Wsh[idx] = W4[idx];

    float acc[4][LL];
    #pragma unroll
    for (int r = 0; r < 4; r++)
        #pragma unroll
        for (int j = 0; j < LL; j++) acc[r][j] = 0.f;

    for (int s = 0; s < NSTAGE; s++) {
        // issue next stage's copy
        if (s + 1 < NSTAGE) {
            float4* dst = Xsh + ((s+1) & 1) * (RPB*KT4);
            #pragma unroll
            for (int i = 0; i < 4; i++) {
                const int c   = tid + 256*i;
                const int r   = c >> 5;
                const int col = c & 31;
                cp_async16(&dst[c],
                           &X4[(size_t)(row0 + r)*(HH/4) + (s+1)*KT4 + col]);
            }
            cp_commit();
            cp_wait1();     // stage s arrived (one group still in flight)
        } else {
            cp_wait0();
        }
        __syncthreads();    // X stage s + (s==0: W) visible to all

        // compute stage s: warp covers 4 rows, lane = float4 col within stage
        const float4* Xs = Xsh + (s & 1)*(RPB*KT4) + warp*4*KT4;
        float4 xv[4];
        #pragma unroll
        for (int r = 0; r < 4; r++) xv[r] = Xs[r*KT4 + lane];
        #pragma unroll
        for (int j = 0; j < LL; j++) {
            const float4 w = Wsh[j*(HH/4) + s*KT4 + lane];
            #pragma unroll
            for (int r = 0; r < 4; r++) {
                acc[r][j] += xv[r].x*w.x;
                acc[r][j] += xv[r].y*w.y;
                acc[r][j] += xv[r].z*w.z;
                acc[r][j] += xv[r].w*w.w;
            }
        }
        __syncthreads();    // done reading buf (s&1) before it is overwritten
    }

    // butterfly reduce: afterwards every lane holds the full sums
    #pragma unroll
    for (int r = 0; r < 4; r++)
        #pragma unroll
        for (int j = 0; j < LL; j++) {
            float v = acc[r][j];
            v += __shfl_xor_sync(0xffffffffu, v, 16);
            v += __shfl_xor_sync(0xffffffffu, v, 8);
            v += __shfl_xor_sync(0xffffffffu, v, 4);
            v += __shfl_xor_sync(0xffffffffu, v, 2);
            v += __shfl_xor_sync(0xffffffffu, v, 1);
            acc[r][j] = v;
        }

    // lanes 0..8 each store column j for the 4 rows (coalesced 36-float run)
    if (lane < LL) {
        const float bj = __ldg(&bias[lane]);
        const int rowb = row0 + warp*4;
        #pragma unroll
        for (int r = 0; r < 4; r++)
            g_logits[(size_t)(rowb + r)*LL + lane] = acc[r][lane] + bj;
    }
}

// ---------------------------------------------------------------------------
// Kernel 2: per-(batch,chunk) fold steps t0..t0+n-1 into a 9x9 transfer matrix
// in the (logsumexp,+) semiring. Barrier-free: thread holds M[i][j] in a
// register; M[i][k] gathered via __shfl_sync within a 9-lane row group.
// 3 warps x 3 rows/warp (lanes 0..26 active). Masked steps are exact copies.
// ---------------------------------------------------------------------------
__global__ __launch_bounds__(96) void k_chunks(const float* __restrict__ trans,
                                               const int* __restrict__ mask) {
    __shared__ float emit_sh[CHUNK][LL];
    __shared__ int   mask_sh[CHUNK];

    const int b  = blockIdx.x / NC;
    const int c  = blockIdx.x % NC;
    const int t0 = 1 + c * CHUNK;
    const int n  = min(SS, t0 + CHUNK) - t0;   // 32 (last chunk 31)
    const int tid  = threadIdx.x;
    const int warp = tid >> 5;
    const int lane = tid & 31;

    if (blockIdx.x == 0 && tid == 0) g_ticket = 0;   // reset for fused k_final

    for (int idx = tid; idx < n * LL; idx += 96)
        emit_sh[idx / LL][idx % LL] =
            g_logits[((size_t)b*SS + t0 + idx/LL)*LL + (idx % LL)];
    for (int idx = tid; idx < n; idx += 96)
        mask_sh[idx] = mask[b*SS + t0 + idx];
    __syncthreads();

    const bool act  = lane < 27;
    const int  base = (lane / LL) * LL;       // first lane of this row group
    const int  i    = warp * 3 + lane / LL;   // row (valid when act)
    const int  j    = lane % LL;              // column

    float tcol[LL];                            // trans[k][j]
    #pragma unroll
    for (int k = 0; k < LL; k++) tcol[k] = trans[k*LL + j];

    // init with first step t0: M[i][j] = trans[i][j] + emit[j], or identity
    float cur = (mask_sh[0] > 0) ? (trans[i*LL + j] + emit_sh[0][j])
                                 : ((i == j) ? 0.f : -1e30f);

    for (int s = 1; s < n; s++) {
        float v[LL];
        #pragma unroll
        for (int k = 0; k < LL; k++)
            v[k] = __shfl_sync(0xffffffffu, cur, base + k) + tcol[k];
        float mx = v[0];
        #pragma unroll
        for (int k = 1; k < LL; k++) mx = fmaxf(mx, v[k]);
        float ssum = 0.f;
        #pragma unroll
        for (int k = 0; k < LL; k++) ssum += __expf(v[k] - mx);
        const float newv = emit_sh[s][j] + mx + __logf(ssum);
        cur = (mask_sh[s] > 0) ? newv : cur;   // exact copy when masked
    }

    if (act) g_chunks[(size_t)(b*NC + c)*81 + i*LL + j] = cur;
}

// ---------------------------------------------------------------------------
// Kernel 3 (fused final+mean): per-batch gold score + log-partition via chunk
// composition; last block reduces g_pb -> out.
// NOTE: labels are int32 (JAX x64 disabled makes .astype(int64) a no-op).
// ---------------------------------------------------------------------------
__global__ __launch_bounds__(256) void k_final(const float* __restrict__ trans,
                                               const int* __restrict__ mask,
                                               const int* __restrict__ labels,
                                               const float* __restrict__ startv,
                                               const float* __restrict__ endv,
                                               float* __restrict__ out) {
    const int b = blockIdx.x, tid = threadIdx.x;
    __shared__ float redf[256];
    __shared__ int   redi[256];
    __shared__ float alpha_sh[LL];

    float part = 0.f; int cnt = 0;
    for (int t = tid; t < SS; t += 256) {
        const int tag = labels[(size_t)b*SS + t];
        const int mi  = mask[b*SS + t];
        const float m = (mi > 0) ? 1.f : 0.f;
        cnt += (mi > 0);
        part += m * g_logits[((size_t)b*SS + t)*LL + tag];
        if (t >= 1) {
            const int tagp = labels[(size_t)b*SS + t - 1];
            part += m * trans[tagp*LL + tag];
        }
    }
    redf[tid] = part; redi[tid] = cnt;
    __syncthreads();
    for (int s2 = 128; s2 > 0; s2 >>= 1) {
        if (tid < s2) { redf[tid] += redf[tid + s2]; redi[tid] += redi[tid + s2]; }
        __syncthreads();
    }

    // alpha0 = feats[0] + start (mask not applied at t=0, per reference)
    if (tid < LL) alpha_sh[tid] = g_logits[((size_t)b*SS)*LL + tid] + startv[tid];
    __syncthreads();

    for (int c = 0; c < NC; c++) {
        float newv = 0.f;
        if (tid < LL) {
            const float* P = &g_chunks[(size_t)(b*NC + c)*81];
            float v[LL];
            float mx = -1e30f;
            #pragma unroll
            for (int k = 0; k < LL; k++) {
                v[k] = alpha_sh[k] + P[k*LL + tid];
                mx = fmaxf(mx, v[k]);
            }
            float s = 0.f;
            #pragma unroll
            for (int k = 0; k < LL; k++) s += __expf(v[k] - mx);
            newv = mx + __logf(s);
        }
        __syncthreads();
        if (tid < LL) alpha_sh[tid] = newv;
        __syncthreads();
    }

    if (tid == 0) {
        float mx = -1e30f;
        #pragma unroll
        for (int j = 0; j < LL; j++) mx = fmaxf(mx, alpha_sh[j] + endv[j]);
        float s = 0.f;
        #pragma unroll
        for (int j = 0; j < LL; j++) s += __expf(alpha_sh[j] + endv[j] - mx);
        const float norm = mx + __logf(s);

        int last_idx = redi[0] - 1; if (last_idx < 0) last_idx = 0;
        const int tag0 = labels[(size_t)b*SS];
        const int tagL = labels[(size_t)b*SS + last_idx];
        g_pb[b] = norm - (redf[0] + startv[tag0] + endv[tagL]);

        __threadfence();
        const int ticket = atomicAdd(&g_ticket, 1);
        if (ticket == BB - 1) {           // last block: reduce to scalar
            float sum = 0.f;
            #pragma unroll
            for (int ib = 0; ib < BB; ib++) sum += g_pb[ib];
            out[0] = sum * (1.f / BB);
        }
    }
}

extern "C" void kernel_launch(void* const* d_in, const int* in_sizes, int n_in,
                              void* d_out, int out_size) {
    const float* X      = (const float*)d_in[0];
    const int*   labels = (const int*)  d_in[1];   // int32 on device (JAX x64 off)
    const int*   mask   = (const int*)  d_in[2];
    const float* W      = (const float*)d_in[3];
    const float* bias   = (const float*)d_in[4];
    const float* trans  = (const float*)d_in[5];
    const float* startv = (const float*)d_in[6];
    const float* endv   = (const float*)d_in[7];

    const int smem_bytes = (LL*(HH/4) + 2*RPB*KT4) * sizeof(float4);  // 69632
    cudaFuncSetAttribute(k_logits, cudaFuncAttributeMaxDynamicSharedMemorySize,
                         smem_bytes);

    k_logits<<<(BB*SS)/RPB, 256, smem_bytes>>>(X, W, bias);
    k_chunks<<<BB*NC, 96>>>(trans, mask);
    k_final<<<BB, 256>>>(trans, mask, labels, startv, endv, (float*)d_out);
}

// round 11
// speedup vs baseline: 1.1279x; 1.1279x over previous
#include <cuda_runtime.h>
#include <cstdint>

#define BB 64
#define SS 512
#define HH 1024
#define LL 9
#define NC 16
#define CHUNK 32

#define RPW 2            // rows per warp in k_logits
#define RPB 16           // rows per block (8 warps * 2)

// scratch (static __device__ — no allocations)
__device__ float g_logits[BB*SS*LL];     // [B,S,L] fc outputs
__device__ float g_chunks[BB*NC*81];     // per-(batch,chunk) 9x9 log-semiring transfer matrices
__device__ float g_pb[BB];               // per-batch (norm - score)
__device__ int   g_ticket;               // last-block ticket for fused mean

// ---------------------------------------------------------------------------
// Kernel 1: logits[b,s,j] = dot(inputs[b,s,:], W[j,:]) + bias[j]
// 256 threads, 8 warps x 2 rows = 16 rows/block, grid 2048.
// X read directly via LDG.128 (streamed, no reuse -> no smem staging).
// W (36 KB) staged in SMEM. Small per-thread state (acc 18 regs) +
// launch_bounds(256,5) -> 40 warps/SM to cover load/LDS latency.
// ---------------------------------------------------------------------------
__global__ __launch_bounds__(256, 5) void k_logits(const float* __restrict__ X,
                                                   const float* __restrict__ W,
                                                   const float* __restrict__ bias) {
    __shared__ float4 Wsh[LL*(HH/4)];   // 9*256 float4 = 36 KB
    const float4* W4 = reinterpret_cast<const float4*>(W);
    for (int idx = threadIdx.x; idx < LL*(HH/4); idx += 256) Wsh[idx] = W4[idx];
    __syncthreads();

    const int warp = threadIdx.x >> 5;
    const int lane = threadIdx.x & 31;
    const int row0 = blockIdx.x * RPB + warp * RPW;
    const float4* X4 = reinterpret_cast<const float4*>(X);

    float acc[RPW][LL];
    #pragma unroll
    for (int r = 0; r < RPW; r++)
        #pragma unroll
        for (int j = 0; j < LL; j++) acc[r][j] = 0.f;

    #pragma unroll 2
    for (int k = 0; k < 8; k++) {
        const int col = k * 32 + lane;   // float4 column, 0..255
        float4 xv[RPW];
        #pragma unroll
        for (int r = 0; r < RPW; r++)
            xv[r] = X4[(size_t)(row0 + r) * (HH/4) + col];
        #pragma unroll
        for (int j = 0; j < LL; j++) {
            const float4 w = Wsh[j*(HH/4) + col];
            #pragma unroll
            for (int r = 0; r < RPW; r++) {
                acc[r][j] += xv[r].x*w.x;
                acc[r][j] += xv[r].y*w.y;
                acc[r][j] += xv[r].z*w.z;
                acc[r][j] += xv[r].w*w.w;
            }
        }
    }

    // butterfly reduce: afterwards every lane holds the full sums
    #pragma unroll
    for (int r = 0; r < RPW; r++)
        #pragma unroll
        for (int j = 0; j < LL; j++) {
            float v = acc[r][j];
            v += __shfl_xor_sync(0xffffffffu, v, 16);
            v += __shfl_xor_sync(0xffffffffu, v, 8);
            v += __shfl_xor_sync(0xffffffffu, v, 4);
            v += __shfl_xor_sync(0xffffffffu, v, 2);
            v += __shfl_xor_sync(0xffffffffu, v, 1);
            acc[r][j] = v;
        }

    // lanes 0..8 each store column j for the 2 rows (coalesced 18-float run)
    if (lane < LL) {
        const float bj = __ldg(&bias[lane]);
        #pragma unroll
        for (int r = 0; r < RPW; r++)
            g_logits[(size_t)(row0 + r)*LL + lane] = acc[r][lane] + bj;
    }
}

// ---------------------------------------------------------------------------
// Kernel 2: per-(batch,chunk) fold steps t0..t0+n-1 into a 9x9 transfer matrix
// in the (logsumexp,+) semiring. Barrier-free: thread holds M[i][j] in a
// register; M[i][k] gathered via __shfl_sync within a 9-lane row group.
// 3 warps x 3 rows/warp (lanes 0..26 active). Masked steps are exact copies.
// ---------------------------------------------------------------------------
__global__ __launch_bounds__(96) void k_chunks(const float* __restrict__ trans,
                                               const int* __restrict__ mask) {
    __shared__ float emit_sh[CHUNK][LL];
    __shared__ int   mask_sh[CHUNK];

    const int b  = blockIdx.x / NC;
    const int c  = blockIdx.x % NC;
    const int t0 = 1 + c * CHUNK;
    const int n  = min(SS, t0 + CHUNK) - t0;   // 32 (last chunk 31)
    const int tid  = threadIdx.x;
    const int warp = tid >> 5;
    const int lane = tid & 31;

    if (blockIdx.x == 0 && tid == 0) g_ticket = 0;   // reset for fused k_final

    for (int idx = tid; idx < n * LL; idx += 96)
        emit_sh[idx / LL][idx % LL] =
            g_logits[((size_t)b*SS + t0 + idx/LL)*LL + (idx % LL)];
    for (int idx = tid; idx < n; idx += 96)
        mask_sh[idx] = mask[b*SS + t0 + idx];
    __syncthreads();

    const bool act  = lane < 27;
    const int  base = (lane / LL) * LL;       // first lane of this row group
    const int  i    = warp * 3 + lane / LL;   // row (valid when act)
    const int  j    = lane % LL;              // column

    float tcol[LL];                            // trans[k][j]
    #pragma unroll
    for (int k = 0; k < LL; k++) tcol[k] = trans[k*LL + j];

    // init with first step t0: M[i][j] = trans[i][j] + emit[j], or identity
    float cur = (mask_sh[0] > 0) ? (trans[i*LL + j] + emit_sh[0][j])
                                 : ((i == j) ? 0.f : -1e30f);

    for (int s = 1; s < n; s++) {
        float v[LL];
        #pragma unroll
        for (int k = 0; k < LL; k++)
            v[k] = __shfl_sync(0xffffffffu, cur, base + k) + tcol[k];
        float mx = v[0];
        #pragma unroll
        for (int k = 1; k < LL; k++) mx = fmaxf(mx, v[k]);
        float ssum = 0.f;
        #pragma unroll
        for (int k = 0; k < LL; k++) ssum += __expf(v[k] - mx);
        const float newv = emit_sh[s][j] + mx + __logf(ssum);
        cur = (mask_sh[s] > 0) ? newv : cur;   // exact copy when masked
    }

    if (act) g_chunks[(size_t)(b*NC + c)*81 + i*LL + j] = cur;
}

// ---------------------------------------------------------------------------
// Kernel 3 (fused final+mean): per-batch gold score + log-partition via chunk
// composition; last block reduces g_pb -> out.
// NOTE: labels are int32 (JAX x64 disabled makes .astype(int64) a no-op).
// ---------------------------------------------------------------------------
__global__ __launch_bounds__(256) void k_final(const float* __restrict__ trans,
                                               const int* __restrict__ mask,
                                               const int* __restrict__ labels,
                                               const float* __restrict__ startv,
                                               const float* __restrict__ endv,
                                               float* __restrict__ out) {
    const int b = blockIdx.x, tid = threadIdx.x;
    __shared__ float redf[256];
    __shared__ int   redi[256];
    __shared__ float alpha_sh[LL];

    float part = 0.f; int cnt = 0;
    for (int t = tid; t < SS; t += 256) {
        const int tag = labels[(size_t)b*SS + t];
        const int mi  = mask[b*SS + t];
        const float m = (mi > 0) ? 1.f : 0.f;
        cnt += (mi > 0);
        part += m * g_logits[((size_t)b*SS + t)*LL + tag];
        if (t >= 1) {
            const int tagp = labels[(size_t)b*SS + t - 1];
            part += m * trans[tagp*LL + tag];
        }
    }
    redf[tid] = part; redi[tid] = cnt;
    __syncthreads();
    for (int s2 = 128; s2 > 0; s2 >>= 1) {
        if (tid < s2) { redf[tid] += redf[tid + s2]; redi[tid] += redi[tid + s2]; }
        __syncthreads();
    }

    // alpha0 = feats[0] + start (mask not applied at t=0, per reference)
    if (tid < LL) alpha_sh[tid] = g_logits[((size_t)b*SS)*LL + tid] + startv[tid];
    __syncthreads();

    for (int c = 0; c < NC; c++) {
        float newv = 0.f;
        if (tid < LL) {
            const float* P = &g_chunks[(size_t)(b*NC + c)*81];
            float v[LL];
            float mx = -1e30f;
            #pragma unroll
            for (int k = 0; k < LL; k++) {
                v[k] = alpha_sh[k] + P[k*LL + tid];
                mx = fmaxf(mx, v[k]);
            }
            float s = 0.f;
            #pragma unroll
            for (int k = 0; k < LL; k++) s += __expf(v[k] - mx);
            newv = mx + __logf(s);
        }
        __syncthreads();
        if (tid < LL) alpha_sh[tid] = newv;
        __syncthreads();
    }

    if (tid == 0) {
        float mx = -1e30f;
        #pragma unroll
        for (int j = 0; j < LL; j++) mx = fmaxf(mx, alpha_sh[j] + endv[j]);
        float s = 0.f;
        #pragma unroll
        for (int j = 0; j < LL; j++) s += __expf(alpha_sh[j] + endv[j] - mx);
        const float norm = mx + __logf(s);

        int last_idx = redi[0] - 1; if (last_idx < 0) last_idx = 0;
        const int tag0 = labels[(size_t)b*SS];
        const int tagL = labels[(size_t)b*SS + last_idx];
        g_pb[b] = norm - (redf[0] + startv[tag0] + endv[tagL]);

        __threadfence();
        const int ticket = atomicAdd(&g_ticket, 1);
        if (ticket == BB - 1) {           // last block: reduce to scalar
            float sum = 0.f;
            #pragma unroll
            for (int ib = 0; ib < BB; ib++) sum += g_pb[ib];
            out[0] = sum * (1.f / BB);
        }
    }
}

extern "C" void kernel_launch(void* const* d_in, const int* in_sizes, int n_in,
                              void* d_out, int out_size) {
    const float* X      = (const float*)d_in[0];
    const int*   labels = (const int*)  d_in[1];   // int32 on device (JAX x64 off)
    const int*   mask   = (const int*)  d_in[2];
    const float* W      = (const float*)d_in[3];
    const float* bias   = (const float*)d_in[4];
    const float* trans  = (const float*)d_in[5];
    const float* startv = (const float*)d_in[6];
    const float* endv   = (const float*)d_in[7];

    k_logits<<<(BB*SS)/RPB, 256>>>(X, W, bias);
    k_chunks<<<BB*NC, 96>>>(trans, mask);
    k_final<<<BB, 256>>>(trans, mask, labels, startv, endv, (float*)d_out);
}

// round 13
// speedup vs baseline: 1.1736x; 1.0405x over previous
#include <cuda_runtime.h>
#include <cstdint>

#define BB 64
#define SS 512
#define HH 1024
#define LL 9
#define NC 16
#define CHUNK 32

#define RPW 2            // rows per warp in k_logits
#define RPB 16           // rows per block (8 warps * 2)

// scratch (static __device__ — no allocations)
__device__ float g_logits[BB*SS*LL];     // [B,S,L] fc outputs
__device__ float g_chunks[BB*NC*81];     // per-(batch,chunk) 9x9 transfer matrices
__device__ float g_pb[BB];               // per-batch (norm - score)
__device__ int   g_cnt[BB];              // per-batch chunk-completion counters
__device__ int   g_ticket;               // global ticket for final mean

// ---------------------------------------------------------------------------
// Kernel 1: logits[b,s,j] = dot(inputs[b,s,:], W[j,:]) + bias[j]
// 8 warps x 2 rows = 16 rows/block. W (36 KB) in SMEM.
// Register double-buffer: the 4 LDG.128 for the NEXT 2 k-iters are issued
// before computing the current 2 from resident regs -> 8 loads in flight.
// FMA order identical to prior rounds (bit-exact logits).
// Also resets the ticket counters used by the fused CRF kernel.
// ---------------------------------------------------------------------------
__global__ __launch_bounds__(256, 4) void k_logits(const float* __restrict__ X,
                                                   const float* __restrict__ W,
                                                   const float* __restrict__ bias) {
    if (blockIdx.x == 0) {
        if (threadIdx.x < BB) g_cnt[threadIdx.x] = 0;
        if (threadIdx.x == BB) g_ticket = 0;
    }

    __shared__ float4 Wsh[LL*(HH/4)];   // 9*256 float4 = 36 KB
    const float4* W4 = reinterpret_cast<const float4*>(W);
    for (int idx = threadIdx.x; idx < LL*(HH/4); idx += 256) Wsh[idx] = W4[idx];
    __syncthreads();

    const int warp = threadIdx.x >> 5;
    const int lane = threadIdx.x & 31;
    const int row0 = blockIdx.x * RPB + warp * RPW;
    const float4* Xr0 = reinterpret_cast<const float4*>(X) + (size_t)row0 * (HH/4);
    const float4* Xr1 = Xr0 + (HH/4);

    float acc[RPW][LL];
    #pragma unroll
    for (int r = 0; r < RPW; r++)
        #pragma unroll
        for (int j = 0; j < LL; j++) acc[r][j] = 0.f;

    // prologue: k-iters 0,1
    float4 cur[2][RPW], nxt[2][RPW];
    cur[0][0] = Xr0[lane];        cur[0][1] = Xr1[lane];
    cur[1][0] = Xr0[32 + lane];   cur[1][1] = Xr1[32 + lane];

    #pragma unroll
    for (int g = 0; g < 4; g++) {
        if (g < 3) {               // prefetch k-iters 2g+2, 2g+3
            const int c0 = (2*g + 2)*32 + lane;
            nxt[0][0] = Xr0[c0];      nxt[0][1] = Xr1[c0];
            nxt[1][0] = Xr0[c0 + 32]; nxt[1][1] = Xr1[c0 + 32];
        }
        #pragma unroll
        for (int u = 0; u < 2; u++) {
            const int col = (2*g + u)*32 + lane;
            #pragma unroll
            for (int j = 0; j < LL; j++) {
                const float4 w = Wsh[j*(HH/4) + col];
                #pragma unroll
                for (int r = 0; r < RPW; r++) {
                    acc[r][j] += cur[u][r].x*w.x;
                    acc[r][j] += cur[u][r].y*w.y;
                    acc[r][j] += cur[u][r].z*w.z;
                    acc[r][j] += cur[u][r].w*w.w;
                }
            }
        }
        #pragma unroll
        for (int u = 0; u < 2; u++)
            #pragma unroll
            for (int r = 0; r < RPW; r++) cur[u][r] = nxt[u][r];
    }

    // butterfly reduce: afterwards every lane holds the full sums
    #pragma unroll
    for (int r = 0; r < RPW; r++)
        #pragma unroll
        for (int j = 0; j < LL; j++) {
            float v = acc[r][j];
            v += __shfl_xor_sync(0xffffffffu, v, 16);
            v += __shfl_xor_sync(0xffffffffu, v, 8);
            v += __shfl_xor_sync(0xffffffffu, v, 4);
            v += __shfl_xor_sync(0xffffffffu, v, 2);
            v += __shfl_xor_sync(0xffffffffu, v, 1);
            acc[r][j] = v;
        }

    // lanes 0..8 each store column j for the 2 rows
    if (lane < LL) {
        const float bj = __ldg(&bias[lane]);
        #pragma unroll
        for (int r = 0; r < RPW; r++)
            g_logits[(size_t)(row0 + r)*LL + lane] = acc[r][lane] + bj;
    }
}

// ---------------------------------------------------------------------------
// Kernel 2 (fused chunks + final + mean):
// Each block folds one (batch, chunk) into a 9x9 transfer matrix (shuffle
// scan, 3 warps x 3 rows, lanes 0..26). The LAST block to finish a batch
// (per-batch ticket) composes the 16 matrices, computes the gold score,
// and writes norm-score; the globally-last batch writes the mean.
// NOTE: labels are int32 (JAX x64 disabled makes .astype(int64) a no-op).
// ---------------------------------------------------------------------------
__global__ __launch_bounds__(96) void k_crf(const float* __restrict__ trans,
                                            const int* __restrict__ mask,
                                            const int* __restrict__ labels,
                                            const float* __restrict__ startv,
                                            const float* __restrict__ endv,
                                            float* __restrict__ out) {
    __shared__ float emit_sh[CHUNK][LL];
    __shared__ int   mask_sh[CHUNK];

    const int b  = blockIdx.x / NC;
    const int c  = blockIdx.x % NC;
    const int t0 = 1 + c * CHUNK;
    const int n  = min(SS, t0 + CHUNK) - t0;   // 32 (last chunk 31)
    const int tid  = threadIdx.x;
    const int warp = tid >> 5;
    const int lane = tid & 31;

    for (int idx = tid; idx < n * LL; idx += 96)
        emit_sh[idx / LL][idx % LL] =
            g_logits[((size_t)b*SS + t0 + idx/LL)*LL + (idx % LL)];
    for (int idx = tid; idx < n; idx += 96)
        mask_sh[idx] = mask[b*SS + t0 + idx];
    __syncthreads();

    const bool act  = lane < 27;
    const int  base = (lane / LL) * LL;       // first lane of this row group
    const int  i    = warp * 3 + lane / LL;   // row (valid when act)
    const int  j    = lane % LL;              // column

    float tcol[LL];                            // trans[k][j]
    #pragma unroll
    for (int k = 0; k < LL; k++) tcol[k] = trans[k*LL + j];

    float cur = (mask_sh[0] > 0) ? (trans[i*LL + j] + emit_sh[0][j])
                                 : ((i == j) ? 0.f : -1e30f);

    for (int s = 1; s < n; s++) {
        float v[LL];
        #pragma unroll
        for (int k = 0; k < LL; k++)
            v[k] = __shfl_sync(0xffffffffu, cur, base + k) + tcol[k];
        float mx = v[0];
        #pragma unroll
        for (int k = 1; k < LL; k++) mx = fmaxf(mx, v[k]);
        float ssum = 0.f;
        #pragma unroll
        for (int k = 0; k < LL; k++) ssum += __expf(v[k] - mx);
        const float newv = emit_sh[s][j] + mx + __logf(ssum);
        cur = (mask_sh[s] > 0) ? newv : cur;   // exact copy when masked
    }

    if (act) g_chunks[(size_t)(b*NC + c)*81 + i*LL + j] = cur;

    // ---- per-batch ticket: last chunk block of batch b does the finale ----
    __threadfence();
    __syncthreads();
    __shared__ int is_last;
    if (tid == 0) is_last = (atomicAdd(&g_cnt[b], 1) == NC - 1);
    __syncthreads();
    if (!is_last) return;
    __threadfence();   // order the other blocks' g_chunks stores before our reads

    // gold path score with 96 threads
    __shared__ float redf[96];
    __shared__ int   redi[96];
    __shared__ float alpha_sh[LL];

    float part = 0.f; int cnt = 0;
    for (int t = tid; t < SS; t += 96) {
        const int tag = labels[(size_t)b*SS + t];
        const int mi  = mask[b*SS + t];
        const float m = (mi > 0) ? 1.f : 0.f;
        cnt += (mi > 0);
        part += m * g_logits[((size_t)b*SS + t)*LL + tag];
        if (t >= 1) {
            const int tagp = labels[(size_t)b*SS + t - 1];
            part += m * trans[tagp*LL + tag];
        }
    }
    redf[tid] = part; redi[tid] = cnt;
    __syncthreads();
    for (int s2 = 64; s2 > 0; s2 >>= 1) {
        if (tid < s2 && tid + s2 < 96) {
            redf[tid] += redf[tid + s2];
            redi[tid] += redi[tid + s2];
        }
        __syncthreads();
    }

    // alpha0 = feats[0] + start (mask not applied at t=0, per reference)
    if (tid < LL) alpha_sh[tid] = g_logits[((size_t)b*SS)*LL + tid] + startv[tid];
    __syncthreads();

    for (int cc = 0; cc < NC; cc++) {
        float newv = 0.f;
        if (tid < LL) {
            const float* P = &g_chunks[(size_t)(b*NC + cc)*81];
            float v[LL];
            float mx = -1e30f;
            #pragma unroll
            for (int k = 0; k < LL; k++) {
                v[k] = alpha_sh[k] + P[k*LL + tid];
                mx = fmaxf(mx, v[k]);
            }
            float s = 0.f;
            #pragma unroll
            for (int k = 0; k < LL; k++) s += __expf(v[k] - mx);
            newv = mx + __logf(s);
        }
        __syncthreads();
        if (tid < LL) alpha_sh[tid] = newv;
        __syncthreads();
    }

    if (tid == 0) {
        float mx = -1e30f;
        #pragma unroll
        for (int jj = 0; jj < LL; jj++) mx = fmaxf(mx, alpha_sh[jj] + endv[jj]);
        float s = 0.f;
        #pragma unroll
        for (int jj = 0; jj < LL; jj++) s += __expf(alpha_sh[jj] + endv[jj] - mx);
        const float norm = mx + __logf(s);

        int last_idx = redi[0] - 1; if (last_idx < 0) last_idx = 0;
        const int tag0 = labels[(size_t)b*SS];
        const int tagL = labels[(size_t)b*SS + last_idx];
        g_pb[b] = norm - (redf[0] + startv[tag0] + endv[tagL]);

        __threadfence();
        const int t2 = atomicAdd(&g_ticket, 1);
        if (t2 == BB - 1) {           // globally last batch: reduce to scalar
            __threadfence();
            float sum = 0.f;
            #pragma unroll
            for (int ib = 0; ib < BB; ib++) sum += g_pb[ib];
            out[0] = sum * (1.f / BB);
        }
    }
}

extern "C" void kernel_launch(void* const* d_in, const int* in_sizes, int n_in,
                              void* d_out, int out_size) {
    const float* X      = (const float*)d_in[0];
    const int*   labels = (const int*)  d_in[1];   // int32 on device (JAX x64 off)
    const int*   mask   = (const int*)  d_in[2];
    const float* W      = (const float*)d_in[3];
    const float* bias   = (const float*)d_in[4];
    const float* trans  = (const float*)d_in[5];
    const float* startv = (const float*)d_in[6];
    const float* endv   = (const float*)d_in[7];

    k_logits<<<(BB*SS)/RPB, 256>>>(X, W, bias);
    k_crf<<<BB*NC, 96>>>(trans, mask, labels, startv, endv, (float*)d_out);
}